// round 2
// baseline (speedup 1.0000x reference)
#include <cuda_runtime.h>
#include <cuda_bf16.h>
#include <cstdint>

#define NHEAD 16
#define QLEN  4096
#define KLEN  4096
#define DIM   64
#define BQ    64
#define BK    64
#define NTHREADS 256
#define SMS   68   // smem row stride in floats (float4-aligned, conflict-reducing)

__device__ __forceinline__ float fast_exp2(float x) {
    float y;
    asm("ex2.approx.ftz.f32 %0, %1;" : "=f"(y) : "f"(x));
    return y;
}

extern "C" __global__ void __launch_bounds__(NTHREADS)
flash_fwd_f32(const float* __restrict__ qs, const float* __restrict__ ks,
              const float* __restrict__ vs, const unsigned int* __restrict__ maskw,
              float* __restrict__ out)
{
    extern __shared__ float sm[];
    float* QsT = sm;                  // [DIM][SMS], indexed [d][q]
    float* KsT = QsT + DIM * SMS;     // [DIM][SMS], indexed [d][k]
    float* Vs  = KsT + DIM * SMS;     // [BK][SMS],  indexed [k][d]
    float* Ps  = Vs  + BK  * SMS;     // [BK][SMS],  indexed [k][q]

    const int tid  = threadIdx.x;
    const int ty   = tid >> 4;   // 0..15  -> query group (4 queries)
    const int tx   = tid & 15;   // 0..15  -> key/dim group (4 cols)
    const int head = blockIdx.y;
    const int q0   = blockIdx.x * BQ;

    // fold 1/sqrt(D) and log2(e) into Q so softmax uses ex2 directly
    const float qscale = 0.125f * 1.44269504088896340736f;

    // ---- load Q tile, scaled + transposed into QsT[d][q] ----
    {
        const float* qptr = qs + ((size_t)head * QLEN + q0) * DIM;
        const int c4 = tx * 4;
        #pragma unroll
        for (int rr = 0; rr < 4; rr++) {
            const int r = ty + rr * 16;
            float4 v = *(const float4*)(qptr + (size_t)r * DIM + c4);
            QsT[(c4 + 0) * SMS + r] = v.x * qscale;
            QsT[(c4 + 1) * SMS + r] = v.y * qscale;
            QsT[(c4 + 2) * SMS + r] = v.z * qscale;
            QsT[(c4 + 3) * SMS + r] = v.w * qscale;
        }
    }

    float o[4][4];
    #pragma unroll
    for (int i = 0; i < 4; i++)
        #pragma unroll
        for (int j = 0; j < 4; j++) o[i][j] = 0.0f;

    float mrun[4] = {-1e30f, -1e30f, -1e30f, -1e30f};
    float lrun[4] = {0.0f, 0.0f, 0.0f, 0.0f};

    const float* kbase = ks + (size_t)head * KLEN * DIM;
    const float* vbase = vs + (size_t)head * KLEN * DIM;

    for (int k0 = 0; k0 < KLEN; k0 += BK) {
        __syncthreads();  // prev GEMM2 done: safe to overwrite KsT/Vs/Ps

        // ---- load K tile (transposed) and V tile (natural) ----
        {
            const int c4 = tx * 4;
            #pragma unroll
            for (int rr = 0; rr < 4; rr++) {
                const int r = ty + rr * 16;
                float4 kv = *(const float4*)(kbase + (size_t)(k0 + r) * DIM + c4);
                KsT[(c4 + 0) * SMS + r] = kv.x;
                KsT[(c4 + 1) * SMS + r] = kv.y;
                KsT[(c4 + 2) * SMS + r] = kv.z;
                KsT[(c4 + 3) * SMS + r] = kv.w;
                float4 vv = *(const float4*)(vbase + (size_t)(k0 + r) * DIM + c4);
                *(float4*)&Vs[r * SMS + c4] = vv;
            }
        }
        __syncthreads();

        // ---- GEMM1: S(4x4) = Q_tile @ K_tile^T ----
        float s[4][4];
        #pragma unroll
        for (int i = 0; i < 4; i++)
            #pragma unroll
            for (int j = 0; j < 4; j++) s[i][j] = 0.0f;

        #pragma unroll 8
        for (int d = 0; d < DIM; d++) {
            float4 qf = *(const float4*)&QsT[d * SMS + ty * 4];
            float4 kf = *(const float4*)&KsT[d * SMS + tx * 4];
            s[0][0] += qf.x * kf.x; s[0][1] += qf.x * kf.y;
            s[0][2] += qf.x * kf.z; s[0][3] += qf.x * kf.w;
            s[1][0] += qf.y * kf.x; s[1][1] += qf.y * kf.y;
            s[1][2] += qf.y * kf.z; s[1][3] += qf.y * kf.w;
            s[2][0] += qf.z * kf.x; s[2][1] += qf.z * kf.y;
            s[2][2] += qf.z * kf.z; s[2][3] += qf.z * kf.w;
            s[3][0] += qf.w * kf.x; s[3][1] += qf.w * kf.y;
            s[3][2] += qf.w * kf.z; s[3][3] += qf.w * kf.w;
        }

        // ---- key mask ----
        // Encoding-robust: keys 4t..4t+3 masked iff 32-bit word t of the mask
        // buffer is zero. Correct for all-true masks under BOTH int32-per-key
        // and byte-per-key encodings; never reads past 4KB (valid for both).
        {
            unsigned int w = maskw[(k0 >> 2) + tx];
            if (w == 0u) {
                #pragma unroll
                for (int i = 0; i < 4; i++)
                    #pragma unroll
                    for (int j = 0; j < 4; j++) s[i][j] = -1e30f;
            }
        }

        // ---- online softmax (base-2 domain) ----
        float mt[4], lt[4];
        #pragma unroll
        for (int i = 0; i < 4; i++)
            mt[i] = fmaxf(fmaxf(s[i][0], s[i][1]), fmaxf(s[i][2], s[i][3]));
        #pragma unroll
        for (int ofs = 1; ofs < 16; ofs <<= 1) {
            #pragma unroll
            for (int i = 0; i < 4; i++)
                mt[i] = fmaxf(mt[i], __shfl_xor_sync(0xffffffffu, mt[i], ofs));
        }

        #pragma unroll
        for (int i = 0; i < 4; i++) {
            float mn = fmaxf(mrun[i], mt[i]);
            float al = fast_exp2(mrun[i] - mn);
            mrun[i] = mn;
            #pragma unroll
            for (int j = 0; j < 4; j++) s[i][j] = fast_exp2(s[i][j] - mn);
            lt[i] = (s[i][0] + s[i][1]) + (s[i][2] + s[i][3]);
            lrun[i] *= al;
            #pragma unroll
            for (int j = 0; j < 4; j++) o[i][j] *= al;
        }
        #pragma unroll
        for (int ofs = 1; ofs < 16; ofs <<= 1) {
            #pragma unroll
            for (int i = 0; i < 4; i++)
                lt[i] += __shfl_xor_sync(0xffffffffu, lt[i], ofs);
        }
        #pragma unroll
        for (int i = 0; i < 4; i++) lrun[i] += lt[i];

        // ---- write P transposed: Ps[k][q] ----
        #pragma unroll
        for (int j = 0; j < 4; j++) {
            float4 pv = make_float4(s[0][j], s[1][j], s[2][j], s[3][j]);
            *(float4*)&Ps[(tx * 4 + j) * SMS + ty * 4] = pv;
        }
        __syncthreads();

        // ---- GEMM2: O(4x4) += P_tile @ V_tile ----
        #pragma unroll 8
        for (int k = 0; k < BK; k++) {
            float4 pf = *(const float4*)&Ps[k * SMS + ty * 4];
            float4 vf = *(const float4*)&Vs[k * SMS + tx * 4];
            o[0][0] += pf.x * vf.x; o[0][1] += pf.x * vf.y;
            o[0][2] += pf.x * vf.z; o[0][3] += pf.x * vf.w;
            o[1][0] += pf.y * vf.x; o[1][1] += pf.y * vf.y;
            o[1][2] += pf.y * vf.z; o[1][3] += pf.y * vf.w;
            o[2][0] += pf.z * vf.x; o[2][1] += pf.z * vf.y;
            o[2][2] += pf.z * vf.z; o[2][3] += pf.z * vf.w;
            o[3][0] += pf.w * vf.x; o[3][1] += pf.w * vf.y;
            o[3][2] += pf.w * vf.z; o[3][3] += pf.w * vf.w;
        }
    }

    // ---- epilogue: normalize + store ----
    float* obase = out + ((size_t)head * QLEN + q0) * DIM;
    #pragma unroll
    for (int i = 0; i < 4; i++) {
        float inv = (lrun[i] > 0.0f) ? (1.0f / lrun[i]) : 0.0f;
        float4 r = make_float4(o[i][0] * inv, o[i][1] * inv,
                               o[i][2] * inv, o[i][3] * inv);
        *(float4*)(obase + (size_t)(ty * 4 + i) * DIM + tx * 4) = r;
    }
}

extern "C" void kernel_launch(void* const* d_in, const int* in_sizes, int n_in,
                              void* d_out, int out_size)
{
    const float* qs = (const float*)d_in[0];
    const float* ks = (const float*)d_in[1];
    const float* vs = (const float*)d_in[2];
    const unsigned int* maskw = (const unsigned int*)d_in[3];
    float* out = (float*)d_out;

    const int smem_bytes = (DIM * SMS + DIM * SMS + BK * SMS + BK * SMS) * (int)sizeof(float);
    cudaFuncSetAttribute(flash_fwd_f32, cudaFuncAttributeMaxDynamicSharedMemorySize, smem_bytes);

    dim3 grid(QLEN / BQ, NHEAD);
    flash_fwd_f32<<<grid, NTHREADS, smem_bytes>>>(qs, ks, vs, maskw, out);
}

// round 4
// speedup vs baseline: 3.5377x; 3.5377x over previous
#include <cuda_runtime.h>
#include <cstdint>

#define NHEAD 16
#define QLEN  4096
#define KLEN  4096
#define DIM   64
#define BQ    64
#define BK    64
#define NTHREADS 128
#define NITER (KLEN / BK)

#define KSS 68   // Ks stride (floats): B-frag loads bank == lane (conflict-free)
#define VSS 72   // Vs stride: bank = 8b+g spans 32 banks (conflict-free)
#define PSS 68   // Ps stride: A-frag loads conflict-free

#define KS_OFF 0
#define VS_OFF (64 * KSS)                    // 4352
#define PS_OFF (VS_OFF + 64 * VSS)           // 8960
#define SMEM_FLOATS (PS_OFF + 4 * 16 * PSS)  // 13312
#define SMEM_BYTES  (SMEM_FLOATS * 4)        // 53248

__device__ __forceinline__ uint32_t f2tf(float x) {
    uint32_t r; asm("cvt.rna.tf32.f32 %0, %1;" : "=r"(r) : "f"(x)); return r;
}
__device__ __forceinline__ float fast_exp2(float x) {
    float y; asm("ex2.approx.ftz.f32 %0, %1;" : "=f"(y) : "f"(x)); return y;
}

// D(16x8,f32) += A(16x8,tf32) * B(8x8,tf32)   [row.col]
__device__ __forceinline__ void mma_tf32(float* d, const uint32_t* a,
                                         uint32_t b0, uint32_t b1) {
    asm volatile(
        "mma.sync.aligned.m16n8k8.row.col.f32.tf32.tf32.f32 "
        "{%0,%1,%2,%3}, {%4,%5,%6,%7}, {%8,%9}, {%0,%1,%2,%3};"
        : "+f"(d[0]), "+f"(d[1]), "+f"(d[2]), "+f"(d[3])
        : "r"(a[0]), "r"(a[1]), "r"(a[2]), "r"(a[3]), "r"(b0), "r"(b1));
}

extern "C" __global__ void __launch_bounds__(NTHREADS, 3)
fa_hmma_tf32(const float* __restrict__ qs, const float* __restrict__ ks,
             const float* __restrict__ vs, const unsigned int* __restrict__ maskw,
             float* __restrict__ out)
{
    extern __shared__ float sm[];
    float* Ks = sm + KS_OFF;                 // [64][KSS]  K tile (tf32 bits)
    float* Vs = sm + VS_OFF;                 // [64][VSS]  V tile (tf32 bits)
    uint32_t* KsU = (uint32_t*)Ks;
    uint32_t* VsU = (uint32_t*)Vs;

    const int tid  = threadIdx.x;
    const int w    = tid >> 5;
    const int lane = tid & 31;
    const int g    = lane >> 2;   // groupID: row within 8
    const int b    = lane & 3;    // threadID_in_group: k/col selector

    float* Pw = sm + PS_OFF + w * 16 * PSS;  // warp-private P pad [16][PSS]
    uint32_t* PwU = (uint32_t*)Pw;

    const int head = blockIdx.y;
    const int q0   = blockIdx.x * BQ;
    const int r0   = w * 16 + g;             // local q rows r0, r0+8

    const float qscale = 0.125f * 1.44269504088896340736f;  // 1/sqrt(D) * log2(e)
    const float* qg = qs + ((size_t)head * QLEN + q0) * DIM;
    const float* kg = ks + (size_t)head * KLEN * DIM;
    const float* vg = vs + (size_t)head * KLEN * DIM;

    // ---- persistent Q A-fragments: qa[c] covers k-cols c*8..c*8+7 ----
    uint32_t qa[8][4];
    {
        const float* q_r0 = qg + (size_t)r0 * DIM;
        const float* q_r1 = q_r0 + 8 * DIM;
        #pragma unroll
        for (int c = 0; c < 8; c++) {
            qa[c][0] = f2tf(q_r0[c * 8 + b]     * qscale);
            qa[c][1] = f2tf(q_r1[c * 8 + b]     * qscale);
            qa[c][2] = f2tf(q_r0[c * 8 + b + 4] * qscale);
            qa[c][3] = f2tf(q_r1[c * 8 + b + 4] * qscale);
        }
    }

    float o[8][4];
    #pragma unroll
    for (int j = 0; j < 8; j++)
        #pragma unroll
        for (int e = 0; e < 4; e++) o[j][e] = 0.0f;
    float mrun0 = -1e30f, mrun1 = -1e30f, lrun0 = 0.0f, lrun1 = 0.0f;

    for (int it = 0; it < NITER; it++) {
        const int k0 = it * BK;
        __syncthreads();  // all reads of Ks/Vs from prev iter complete

        // ---- stage K and V tiles (tf32-rounded) ----
        #pragma unroll
        for (int i = 0; i < 8; i++) {
            const int idx = tid + NTHREADS * i;
            const int r = idx >> 4, c4 = (idx & 15) * 4;
            float4 kv = *(const float4*)(kg + (size_t)(k0 + r) * DIM + c4);
            uint4 kt = make_uint4(f2tf(kv.x), f2tf(kv.y), f2tf(kv.z), f2tf(kv.w));
            *(uint4*)&KsU[r * KSS + c4] = kt;
            float4 vv = *(const float4*)(vg + (size_t)(k0 + r) * DIM + c4);
            uint4 vt = make_uint4(f2tf(vv.x), f2tf(vv.y), f2tf(vv.z), f2tf(vv.w));
            *(uint4*)&VsU[r * VSS + c4] = vt;
        }
        __syncthreads();

        // ---- S = Q @ K^T : sacc[j] = S rows {r0,r0+8}, cols j*8+2b+{0,1} ----
        float sacc[8][4];
        #pragma unroll
        for (int j = 0; j < 8; j++)
            #pragma unroll
            for (int e = 0; e < 4; e++) sacc[j][e] = 0.0f;

        #pragma unroll
        for (int c = 0; c < 8; c++) {
            #pragma unroll
            for (int j = 0; j < 8; j++) {
                // B elem (k=c*8+b(+4), n=j*8+g) = K[n][k]
                const uint32_t* kp = &KsU[(j * 8 + g) * KSS + c * 8 + b];
                mma_tf32(sacc[j], qa[c], kp[0], kp[4]);
            }
        }

        // ---- mask (robust word-of-4; all-true -> never taken) ----
        {
            const int kb = k0 >> 2;
            #pragma unroll
            for (int j = 0; j < 8; j++) {
                if (maskw[kb + 2 * j + (b >> 1)] == 0u) {
                    sacc[j][0] = sacc[j][1] = sacc[j][2] = sacc[j][3] = -1e30f;
                }
            }
        }

        // ---- online softmax (log2 domain) ----
        float m0 = -1e30f, m1 = -1e30f;
        #pragma unroll
        for (int j = 0; j < 8; j++) {
            m0 = fmaxf(m0, fmaxf(sacc[j][0], sacc[j][1]));
            m1 = fmaxf(m1, fmaxf(sacc[j][2], sacc[j][3]));
        }
        m0 = fmaxf(m0, __shfl_xor_sync(0xffffffffu, m0, 1));
        m0 = fmaxf(m0, __shfl_xor_sync(0xffffffffu, m0, 2));
        m1 = fmaxf(m1, __shfl_xor_sync(0xffffffffu, m1, 1));
        m1 = fmaxf(m1, __shfl_xor_sync(0xffffffffu, m1, 2));

        const float mn0 = fmaxf(mrun0, m0);
        const float mn1 = fmaxf(mrun1, m1);
        const float a0 = fast_exp2(mrun0 - mn0);
        const float a1 = fast_exp2(mrun1 - mn1);
        mrun0 = mn0; mrun1 = mn1;

        float l0 = 0.0f, l1 = 0.0f;
        #pragma unroll
        for (int j = 0; j < 8; j++) {
            sacc[j][0] = fast_exp2(sacc[j][0] - mn0);
            sacc[j][1] = fast_exp2(sacc[j][1] - mn0);
            sacc[j][2] = fast_exp2(sacc[j][2] - mn1);
            sacc[j][3] = fast_exp2(sacc[j][3] - mn1);
            l0 += sacc[j][0] + sacc[j][1];
            l1 += sacc[j][2] + sacc[j][3];
        }
        l0 += __shfl_xor_sync(0xffffffffu, l0, 1);
        l0 += __shfl_xor_sync(0xffffffffu, l0, 2);
        l1 += __shfl_xor_sync(0xffffffffu, l1, 1);
        l1 += __shfl_xor_sync(0xffffffffu, l1, 2);
        lrun0 = lrun0 * a0 + l0;
        lrun1 = lrun1 * a1 + l1;

        // ---- rescale O ----
        #pragma unroll
        for (int j = 0; j < 8; j++) {
            o[j][0] *= a0; o[j][1] *= a0;
            o[j][2] *= a1; o[j][3] *= a1;
        }

        // ---- P -> warp-private smem pad (tf32-rounded), C-layout cols 2b,2b+1 ----
        #pragma unroll
        for (int j = 0; j < 8; j++) {
            uint32_t p0 = f2tf(sacc[j][0]), p1 = f2tf(sacc[j][1]);
            uint32_t p2 = f2tf(sacc[j][2]), p3 = f2tf(sacc[j][3]);
            *(uint2*)&PwU[g * PSS + j * 8 + 2 * b]       = make_uint2(p0, p1);
            *(uint2*)&PwU[(g + 8) * PSS + j * 8 + 2 * b] = make_uint2(p2, p3);
        }
        __syncwarp();

        // ---- O += P @ V ----
        #pragma unroll
        for (int kc = 0; kc < 8; kc++) {
            uint32_t pa[4];
            pa[0] = PwU[g * PSS + kc * 8 + b];
            pa[1] = PwU[(g + 8) * PSS + kc * 8 + b];
            pa[2] = PwU[g * PSS + kc * 8 + b + 4];
            pa[3] = PwU[(g + 8) * PSS + kc * 8 + b + 4];
            #pragma unroll
            for (int j = 0; j < 8; j++) {
                // B elem (k=kc*8+b(+4), n=j*8+g) = V[k][n]
                const uint32_t v0 = VsU[(kc * 8 + b) * VSS + j * 8 + g];
                const uint32_t v1 = VsU[(kc * 8 + b + 4) * VSS + j * 8 + g];
                mma_tf32(o[j], pa, v0, v1);
            }
        }
        __syncwarp();  // Pw reads done before next iter's overwrite
    }

    // ---- epilogue: normalize + store ----
    {
        const float inv0 = (lrun0 > 0.0f) ? (1.0f / lrun0) : 0.0f;
        const float inv1 = (lrun1 > 0.0f) ? (1.0f / lrun1) : 0.0f;
        float* o_r0 = out + ((size_t)head * QLEN + q0 + r0) * DIM;
        float* o_r1 = o_r0 + 8 * DIM;
        #pragma unroll
        for (int j = 0; j < 8; j++) {
            *(float2*)&o_r0[j * 8 + 2 * b] = make_float2(o[j][0] * inv0, o[j][1] * inv0);
            *(float2*)&o_r1[j * 8 + 2 * b] = make_float2(o[j][2] * inv1, o[j][3] * inv1);
        }
    }
}

extern "C" void kernel_launch(void* const* d_in, const int* in_sizes, int n_in,
                              void* d_out, int out_size)
{
    const float* qs = (const float*)d_in[0];
    const float* ks = (const float*)d_in[1];
    const float* vs = (const float*)d_in[2];
    const unsigned int* maskw = (const unsigned int*)d_in[3];
    float* out = (float*)d_out;

    cudaFuncSetAttribute(fa_hmma_tf32, cudaFuncAttributeMaxDynamicSharedMemorySize, SMEM_BYTES);
    dim3 grid(QLEN / BQ, NHEAD);
    fa_hmma_tf32<<<grid, NTHREADS, SMEM_BYTES>>>(qs, ks, vs, maskw, out);
}

// round 5
// speedup vs baseline: 4.0722x; 1.1511x over previous
#include <cuda_runtime.h>
#include <cstdint>

#define NHEAD 16
#define QLEN  4096
#define KLEN  4096
#define DIM   64
#define BQ    128
#define BK    64
#define NTHREADS 128
#define NITER (KLEN / BK)

#define KSS 68   // K tile stride (floats): B-frag loads conflict-free (bank = 4g+b)
#define VSS 72   // V tile stride: bank = 8b+g+8j spans 32 banks
#define PSS 68   // P pad stride: A-frag loads conflict-free

#define KS_OFF 0
#define VS_OFF (64 * KSS)                     // 4352
#define PS_OFF (VS_OFF + 64 * VSS)            // 8960
#define SMEM_FLOATS (PS_OFF + 4 * 32 * PSS)   // 17664
#define SMEM_BYTES  (SMEM_FLOATS * 4)         // 70656

__device__ __forceinline__ uint32_t f2tf(float x) {
    uint32_t r; asm("cvt.rna.tf32.f32 %0, %1;" : "=r"(r) : "f"(x)); return r;
}
__device__ __forceinline__ float fast_exp2(float x) {
    float y; asm("ex2.approx.ftz.f32 %0, %1;" : "=f"(y) : "f"(x)); return y;
}

// D(16x8,f32) += A(16x8,tf32) * B(8x8,tf32)   [row.col]
__device__ __forceinline__ void mma_tf32(float* d, const uint32_t* a,
                                         uint32_t b0, uint32_t b1) {
    asm volatile(
        "mma.sync.aligned.m16n8k8.row.col.f32.tf32.tf32.f32 "
        "{%0,%1,%2,%3}, {%4,%5,%6,%7}, {%8,%9}, {%0,%1,%2,%3};"
        : "+f"(d[0]), "+f"(d[1]), "+f"(d[2]), "+f"(d[3])
        : "r"(a[0]), "r"(a[1]), "r"(a[2]), "r"(a[3]), "r"(b0), "r"(b1));
}

extern "C" __global__ void __launch_bounds__(NTHREADS, 2)
fa_hmma_m32(const float* __restrict__ qs, const float* __restrict__ ks,
            const float* __restrict__ vs, const unsigned int* __restrict__ maskw,
            float* __restrict__ out)
{
    extern __shared__ float sm[];
    uint32_t* KsU = (uint32_t*)(sm + KS_OFF);   // [64][KSS] K tile (tf32 bits)
    uint32_t* VsU = (uint32_t*)(sm + VS_OFF);   // [64][VSS] V tile (tf32 bits)

    const int tid  = threadIdx.x;
    const int w    = tid >> 5;
    const int lane = tid & 31;
    const int g    = lane >> 2;   // row within 8
    const int b    = lane & 3;    // k/col selector

    uint32_t* PwU = (uint32_t*)(sm + PS_OFF) + w * 32 * PSS;  // warp P pad [32][PSS]

    const int head = blockIdx.y;
    const int q0   = blockIdx.x * BQ;
    const int r0   = w * 32 + g;             // rows r0, +8, +16, +24

    const float qscale = 0.125f * 1.44269504088896340736f;  // 1/sqrt(D) * log2(e)
    const float* qg = qs + ((size_t)head * QLEN + q0) * DIM;
    const float* kg = ks + (size_t)head * KLEN * DIM;
    const float* vg = vs + (size_t)head * KLEN * DIM;

    // ---- persistent Q A-fragments: qa[c][0..3] rows {r0,r0+8}, [4..7] rows {r0+16,r0+24} ----
    uint32_t qa[8][8];
    {
        const float* q0p = qg + (size_t)r0 * DIM;
        const float* q1p = q0p + 8 * DIM;
        const float* q2p = q0p + 16 * DIM;
        const float* q3p = q0p + 24 * DIM;
        #pragma unroll
        for (int c = 0; c < 8; c++) {
            const int k0c = c * 8 + b;
            qa[c][0] = f2tf(q0p[k0c]     * qscale);
            qa[c][1] = f2tf(q1p[k0c]     * qscale);
            qa[c][2] = f2tf(q0p[k0c + 4] * qscale);
            qa[c][3] = f2tf(q1p[k0c + 4] * qscale);
            qa[c][4] = f2tf(q2p[k0c]     * qscale);
            qa[c][5] = f2tf(q3p[k0c]     * qscale);
            qa[c][6] = f2tf(q2p[k0c + 4] * qscale);
            qa[c][7] = f2tf(q3p[k0c + 4] * qscale);
        }
    }

    float o[8][8];
    #pragma unroll
    for (int j = 0; j < 8; j++)
        #pragma unroll
        for (int e = 0; e < 8; e++) o[j][e] = 0.0f;
    float mrun[4] = {-1e30f, -1e30f, -1e30f, -1e30f};
    float lrun[4] = {0.0f, 0.0f, 0.0f, 0.0f};

    for (int it = 0; it < NITER; it++) {
        const int k0 = it * BK;
        __syncthreads();  // all reads of Ks/Vs from prev iter complete

        // ---- stage K and V tiles (tf32-rounded) ----
        #pragma unroll
        for (int i = 0; i < 8; i++) {
            const int idx = tid + NTHREADS * i;
            const int r = idx >> 4, c4 = (idx & 15) * 4;
            float4 kv = *(const float4*)(kg + (size_t)(k0 + r) * DIM + c4);
            *(uint4*)&KsU[r * KSS + c4] =
                make_uint4(f2tf(kv.x), f2tf(kv.y), f2tf(kv.z), f2tf(kv.w));
            float4 vv = *(const float4*)(vg + (size_t)(k0 + r) * DIM + c4);
            *(uint4*)&VsU[r * VSS + c4] =
                make_uint4(f2tf(vv.x), f2tf(vv.y), f2tf(vv.z), f2tf(vv.w));
        }
        __syncthreads();

        // ---- S = Q @ K^T : B fragment shared by both A row-blocks ----
        float sacc[8][8];
        #pragma unroll
        for (int j = 0; j < 8; j++)
            #pragma unroll
            for (int e = 0; e < 8; e++) sacc[j][e] = 0.0f;

        #pragma unroll
        for (int c = 0; c < 8; c++) {
            #pragma unroll
            for (int j = 0; j < 8; j++) {
                const uint32_t* kp = &KsU[(j * 8 + g) * KSS + c * 8 + b];
                const uint32_t kb0 = kp[0], kb1 = kp[4];
                mma_tf32(&sacc[j][0], &qa[c][0], kb0, kb1);
                mma_tf32(&sacc[j][4], &qa[c][4], kb0, kb1);
            }
        }

        // ---- mask (robust word-of-4; all-true -> never taken) ----
        {
            const int kb = k0 >> 2;
            #pragma unroll
            for (int j = 0; j < 8; j++) {
                if (maskw[kb + 2 * j + (b >> 1)] == 0u) {
                    #pragma unroll
                    for (int e = 0; e < 8; e++) sacc[j][e] = -1e30f;
                }
            }
        }

        // ---- online softmax (log2 domain), 4 row-blocks ----
        float m[4] = {-1e30f, -1e30f, -1e30f, -1e30f};
        #pragma unroll
        for (int j = 0; j < 8; j++) {
            #pragma unroll
            for (int i = 0; i < 4; i++)
                m[i] = fmaxf(m[i], fmaxf(sacc[j][2 * i], sacc[j][2 * i + 1]));
        }
        #pragma unroll
        for (int i = 0; i < 4; i++) {
            m[i] = fmaxf(m[i], __shfl_xor_sync(0xffffffffu, m[i], 1));
            m[i] = fmaxf(m[i], __shfl_xor_sync(0xffffffffu, m[i], 2));
        }

        float al[4];
        #pragma unroll
        for (int i = 0; i < 4; i++) {
            const float mn = fmaxf(mrun[i], m[i]);
            al[i] = fast_exp2(mrun[i] - mn);
            mrun[i] = mn;
        }

        float l[4] = {0.0f, 0.0f, 0.0f, 0.0f};
        #pragma unroll
        for (int j = 0; j < 8; j++) {
            #pragma unroll
            for (int i = 0; i < 4; i++) {
                sacc[j][2 * i]     = fast_exp2(sacc[j][2 * i]     - mrun[i]);
                sacc[j][2 * i + 1] = fast_exp2(sacc[j][2 * i + 1] - mrun[i]);
                l[i] += sacc[j][2 * i] + sacc[j][2 * i + 1];
            }
        }
        #pragma unroll
        for (int i = 0; i < 4; i++) {
            l[i] += __shfl_xor_sync(0xffffffffu, l[i], 1);
            l[i] += __shfl_xor_sync(0xffffffffu, l[i], 2);
            lrun[i] = lrun[i] * al[i] + l[i];
        }

        // ---- rescale O ----
        #pragma unroll
        for (int j = 0; j < 8; j++) {
            #pragma unroll
            for (int i = 0; i < 4; i++) {
                o[j][2 * i]     *= al[i];
                o[j][2 * i + 1] *= al[i];
            }
        }

        // ---- P -> warp-private smem pad (tf32-rounded) ----
        #pragma unroll
        for (int j = 0; j < 8; j++) {
            const int col = j * 8 + 2 * b;
            *(uint2*)&PwU[ g       * PSS + col] = make_uint2(f2tf(sacc[j][0]), f2tf(sacc[j][1]));
            *(uint2*)&PwU[(g +  8) * PSS + col] = make_uint2(f2tf(sacc[j][2]), f2tf(sacc[j][3]));
            *(uint2*)&PwU[(g + 16) * PSS + col] = make_uint2(f2tf(sacc[j][4]), f2tf(sacc[j][5]));
            *(uint2*)&PwU[(g + 24) * PSS + col] = make_uint2(f2tf(sacc[j][6]), f2tf(sacc[j][7]));
        }
        __syncwarp();

        // ---- O += P @ V : B fragment shared by both A row-blocks ----
        #pragma unroll
        for (int kc = 0; kc < 8; kc++) {
            uint32_t pa0[4], pa1[4];
            const int kcol = kc * 8 + b;
            pa0[0] = PwU[ g       * PSS + kcol];
            pa0[1] = PwU[(g +  8) * PSS + kcol];
            pa0[2] = PwU[ g       * PSS + kcol + 4];
            pa0[3] = PwU[(g +  8) * PSS + kcol + 4];
            pa1[0] = PwU[(g + 16) * PSS + kcol];
            pa1[1] = PwU[(g + 24) * PSS + kcol];
            pa1[2] = PwU[(g + 16) * PSS + kcol + 4];
            pa1[3] = PwU[(g + 24) * PSS + kcol + 4];
            #pragma unroll
            for (int j = 0; j < 8; j++) {
                const uint32_t v0 = VsU[(kc * 8 + b)     * VSS + j * 8 + g];
                const uint32_t v1 = VsU[(kc * 8 + b + 4) * VSS + j * 8 + g];
                mma_tf32(&o[j][0], pa0, v0, v1);
                mma_tf32(&o[j][4], pa1, v0, v1);
            }
        }
        __syncwarp();  // Pw reads done before next iter's overwrite
    }

    // ---- epilogue: normalize + store ----
    {
        float inv[4];
        #pragma unroll
        for (int i = 0; i < 4; i++) inv[i] = (lrun[i] > 0.0f) ? (1.0f / lrun[i]) : 0.0f;
        float* orow = out + ((size_t)head * QLEN + q0 + r0) * DIM;
        #pragma unroll
        for (int j = 0; j < 8; j++) {
            const int col = j * 8 + 2 * b;
            *(float2*)&orow[ 0 * DIM + col] = make_float2(o[j][0] * inv[0], o[j][1] * inv[0]);
            *(float2*)&orow[ 8 * DIM + col] = make_float2(o[j][2] * inv[1], o[j][3] * inv[1]);
            *(float2*)&orow[16 * DIM + col] = make_float2(o[j][4] * inv[2], o[j][5] * inv[2]);
            *(float2*)&orow[24 * DIM + col] = make_float2(o[j][6] * inv[3], o[j][7] * inv[3]);
        }
    }
}

extern "C" void kernel_launch(void* const* d_in, const int* in_sizes, int n_in,
                              void* d_out, int out_size)
{
    const float* qs = (const float*)d_in[0];
    const float* ks = (const float*)d_in[1];
    const float* vs = (const float*)d_in[2];
    const unsigned int* maskw = (const unsigned int*)d_in[3];
    float* out = (float*)d_out;

    cudaFuncSetAttribute(fa_hmma_m32, cudaFuncAttributeMaxDynamicSharedMemorySize, SMEM_BYTES);
    dim3 grid(QLEN / BQ, NHEAD);
    fa_hmma_m32<<<grid, NTHREADS, SMEM_BYTES>>>(qs, ks, vs, maskw, out);
}

// round 6
// speedup vs baseline: 4.0988x; 1.0065x over previous
#include <cuda_runtime.h>
#include <cstdint>

#define NHEAD 16
#define QLEN  4096
#define KLEN  4096
#define DIM   64
#define BQ    128
#define BK    64
#define NTHREADS 128
#define NITER (KLEN / BK)

#define KSS 68   // K tile stride (floats): B-frag loads conflict-free
#define VSS 72   // V tile stride: conflict-free
#define PSS 68   // P pad stride: A-frag loads conflict-free

#define STAGE_K_FLOATS (64 * KSS)                      // 4352
#define STAGE_FLOATS   (STAGE_K_FLOATS + 64 * VSS)     // 8960
#define PS_OFF         (2 * STAGE_FLOATS)              // 17920
#define SMEM_FLOATS    (PS_OFF + 4 * 32 * PSS)         // 26624
#define SMEM_BYTES     (SMEM_FLOATS * 4)               // 106496

// pre-rounded tf32 K/V scratch (static __device__: allocation-free)
__device__ uint32_t g_Kr[NHEAD * KLEN * DIM];
__device__ uint32_t g_Vr[NHEAD * KLEN * DIM];

__device__ __forceinline__ uint32_t f2tf(float x) {
    uint32_t r; asm("cvt.rna.tf32.f32 %0, %1;" : "=r"(r) : "f"(x)); return r;
}
__device__ __forceinline__ float fast_exp2(float x) {
    float y; asm("ex2.approx.ftz.f32 %0, %1;" : "=f"(y) : "f"(x)); return y;
}
__device__ __forceinline__ uint32_t smem_u32(const void* p) {
    uint32_t a;
    asm("{ .reg .u64 t; cvta.to.shared.u64 t, %1; cvt.u32.u64 %0, t; }" : "=r"(a) : "l"(p));
    return a;
}
__device__ __forceinline__ void cp16(uint32_t dst, const void* src) {
    asm volatile("cp.async.ca.shared.global [%0], [%1], 16;" :: "r"(dst), "l"(src) : "memory");
}
#define CP_COMMIT() asm volatile("cp.async.commit_group;" ::: "memory")
#define CP_WAIT1()  asm volatile("cp.async.wait_group 1;" ::: "memory")

// D(16x8,f32) += A(16x8,tf32) * B(8x8,tf32)   [row.col]
__device__ __forceinline__ void mma_tf32(float* d, const uint32_t* a,
                                         uint32_t b0, uint32_t b1) {
    asm volatile(
        "mma.sync.aligned.m16n8k8.row.col.f32.tf32.tf32.f32 "
        "{%0,%1,%2,%3}, {%4,%5,%6,%7}, {%8,%9}, {%0,%1,%2,%3};"
        : "+f"(d[0]), "+f"(d[1]), "+f"(d[2]), "+f"(d[3])
        : "r"(a[0]), "r"(a[1]), "r"(a[2]), "r"(a[3]), "r"(b0), "r"(b1));
}

// ---- prepass: round K,V to tf32 (rna) once ----
extern "C" __global__ void __launch_bounds__(256)
kv_round(const float* __restrict__ ks, const float* __restrict__ vs)
{
    const size_t i = (size_t)blockIdx.x * blockDim.x + threadIdx.x;  // float4 index
    float4 k = ((const float4*)ks)[i];
    ((uint4*)g_Kr)[i] = make_uint4(f2tf(k.x), f2tf(k.y), f2tf(k.z), f2tf(k.w));
    float4 v = ((const float4*)vs)[i];
    ((uint4*)g_Vr)[i] = make_uint4(f2tf(v.x), f2tf(v.y), f2tf(v.z), f2tf(v.w));
}

extern "C" __global__ void __launch_bounds__(NTHREADS, 2)
fa_hmma_cpa(const float* __restrict__ qs, const unsigned int* __restrict__ maskw,
            float* __restrict__ out)
{
    extern __shared__ float sm[];
    const uint32_t sb = smem_u32(sm);

    const int tid  = threadIdx.x;
    const int w    = tid >> 5;
    const int lane = tid & 31;
    const int g    = lane >> 2;   // row within 8
    const int b    = lane & 3;    // k/col selector

    uint32_t* PwU = (uint32_t*)(sm + PS_OFF) + w * 32 * PSS;  // warp P pad [32][PSS]

    const int head = blockIdx.y;
    const int q0   = blockIdx.x * BQ;
    const int r0   = w * 32 + g;             // rows r0, +8, +16, +24

    const float qscale = 0.125f * 1.44269504088896340736f;  // 1/sqrt(D) * log2(e)
    const float* qg = qs + ((size_t)head * QLEN + q0) * DIM;
    const uint32_t* kg = g_Kr + (size_t)head * KLEN * DIM;
    const uint32_t* vg = g_Vr + (size_t)head * KLEN * DIM;

    // per-thread cp.async source/dest offsets (8 chunks of 16B each for K and V)
    const int srow = tid >> 4;              // 0..7  (row base; +8*i per chunk? no: idx pattern)
    const int scol = (tid & 15) * 4;        // 0..60

    // ---- prologue: prefetch stage 0 ----
    {
        #pragma unroll
        for (int i = 0; i < 8; i++) {
            const int r = srow + 8 * i;
            cp16(sb + (0 * STAGE_FLOATS + r * KSS + scol) * 4, kg + (size_t)r * DIM + scol);
            cp16(sb + (0 * STAGE_FLOATS + STAGE_K_FLOATS + r * VSS + scol) * 4,
                 vg + (size_t)r * DIM + scol);
        }
        CP_COMMIT();
    }

    // ---- persistent Q A-fragments ----
    uint32_t qa[8][8];
    {
        const float* q0p = qg + (size_t)r0 * DIM;
        const float* q1p = q0p + 8 * DIM;
        const float* q2p = q0p + 16 * DIM;
        const float* q3p = q0p + 24 * DIM;
        #pragma unroll
        for (int c = 0; c < 8; c++) {
            const int k0c = c * 8 + b;
            qa[c][0] = f2tf(q0p[k0c]     * qscale);
            qa[c][1] = f2tf(q1p[k0c]     * qscale);
            qa[c][2] = f2tf(q0p[k0c + 4] * qscale);
            qa[c][3] = f2tf(q1p[k0c + 4] * qscale);
            qa[c][4] = f2tf(q2p[k0c]     * qscale);
            qa[c][5] = f2tf(q3p[k0c]     * qscale);
            qa[c][6] = f2tf(q2p[k0c + 4] * qscale);
            qa[c][7] = f2tf(q3p[k0c + 4] * qscale);
        }
    }

    float o[8][8];
    #pragma unroll
    for (int j = 0; j < 8; j++)
        #pragma unroll
        for (int e = 0; e < 8; e++) o[j][e] = 0.0f;
    float mrun[4] = {-1e30f, -1e30f, -1e30f, -1e30f};
    float lrun[4] = {0.0f, 0.0f, 0.0f, 0.0f};

    for (int it = 0; it < NITER; it++) {
        const int k0 = it * BK;
        const int stage = it & 1;

        // ---- prefetch next tile into other stage (clamped re-load at end) ----
        {
            const int knx = (it + 1 < NITER ? it + 1 : it) * BK;
            const uint32_t sbase = sb + ((1 - stage) * STAGE_FLOATS) * 4;
            #pragma unroll
            for (int i = 0; i < 8; i++) {
                const int r = srow + 8 * i;
                cp16(sbase + (r * KSS + scol) * 4, kg + (size_t)(knx + r) * DIM + scol);
                cp16(sbase + (STAGE_K_FLOATS + r * VSS + scol) * 4,
                     vg + (size_t)(knx + r) * DIM + scol);
            }
            CP_COMMIT();
        }
        CP_WAIT1();          // stage `stage` data landed (this thread)
        __syncthreads();     // all threads' stage data visible; prev-iter reads done

        const uint32_t* KsU = (const uint32_t*)(sm + stage * STAGE_FLOATS);
        const uint32_t* VsU = KsU + STAGE_K_FLOATS;

        // ---- S = Q @ K^T : B fragment shared by both A row-blocks ----
        float sacc[8][8];
        #pragma unroll
        for (int j = 0; j < 8; j++)
            #pragma unroll
            for (int e = 0; e < 8; e++) sacc[j][e] = 0.0f;

        #pragma unroll
        for (int c = 0; c < 8; c++) {
            #pragma unroll
            for (int j = 0; j < 8; j++) {
                const uint32_t* kp = &KsU[(j * 8 + g) * KSS + c * 8 + b];
                const uint32_t kb0 = kp[0], kb1 = kp[4];
                mma_tf32(&sacc[j][0], &qa[c][0], kb0, kb1);
                mma_tf32(&sacc[j][4], &qa[c][4], kb0, kb1);
            }
        }

        // ---- mask (robust word-of-4; all-true -> never taken) ----
        {
            const int kb = k0 >> 2;
            #pragma unroll
            for (int j = 0; j < 8; j++) {
                if (maskw[kb + 2 * j + (b >> 1)] == 0u) {
                    #pragma unroll
                    for (int e = 0; e < 8; e++) sacc[j][e] = -1e30f;
                }
            }
        }

        // ---- online softmax (log2 domain), 4 row-blocks ----
        float m[4] = {-1e30f, -1e30f, -1e30f, -1e30f};
        #pragma unroll
        for (int j = 0; j < 8; j++) {
            #pragma unroll
            for (int i = 0; i < 4; i++)
                m[i] = fmaxf(m[i], fmaxf(sacc[j][2 * i], sacc[j][2 * i + 1]));
        }
        #pragma unroll
        for (int i = 0; i < 4; i++) {
            m[i] = fmaxf(m[i], __shfl_xor_sync(0xffffffffu, m[i], 1));
            m[i] = fmaxf(m[i], __shfl_xor_sync(0xffffffffu, m[i], 2));
        }

        float al[4];
        #pragma unroll
        for (int i = 0; i < 4; i++) {
            const float mn = fmaxf(mrun[i], m[i]);
            al[i] = fast_exp2(mrun[i] - mn);
            mrun[i] = mn;
        }

        float l[4] = {0.0f, 0.0f, 0.0f, 0.0f};
        #pragma unroll
        for (int j = 0; j < 8; j++) {
            #pragma unroll
            for (int i = 0; i < 4; i++) {
                sacc[j][2 * i]     = fast_exp2(sacc[j][2 * i]     - mrun[i]);
                sacc[j][2 * i + 1] = fast_exp2(sacc[j][2 * i + 1] - mrun[i]);
                l[i] += sacc[j][2 * i] + sacc[j][2 * i + 1];
            }
        }
        #pragma unroll
        for (int i = 0; i < 4; i++) {
            l[i] += __shfl_xor_sync(0xffffffffu, l[i], 1);
            l[i] += __shfl_xor_sync(0xffffffffu, l[i], 2);
            lrun[i] = lrun[i] * al[i] + l[i];
        }

        // ---- rescale O ----
        #pragma unroll
        for (int j = 0; j < 8; j++) {
            #pragma unroll
            for (int i = 0; i < 4; i++) {
                o[j][2 * i]     *= al[i];
                o[j][2 * i + 1] *= al[i];
            }
        }

        // ---- P -> warp-private smem pad (tf32-rounded) ----
        #pragma unroll
        for (int j = 0; j < 8; j++) {
            const int col = j * 8 + 2 * b;
            *(uint2*)&PwU[ g       * PSS + col] = make_uint2(f2tf(sacc[j][0]), f2tf(sacc[j][1]));
            *(uint2*)&PwU[(g +  8) * PSS + col] = make_uint2(f2tf(sacc[j][2]), f2tf(sacc[j][3]));
            *(uint2*)&PwU[(g + 16) * PSS + col] = make_uint2(f2tf(sacc[j][4]), f2tf(sacc[j][5]));
            *(uint2*)&PwU[(g + 24) * PSS + col] = make_uint2(f2tf(sacc[j][6]), f2tf(sacc[j][7]));
        }
        __syncwarp();

        // ---- O += P @ V : B fragment shared by both A row-blocks ----
        #pragma unroll
        for (int kc = 0; kc < 8; kc++) {
            uint32_t pa0[4], pa1[4];
            const int kcol = kc * 8 + b;
            pa0[0] = PwU[ g       * PSS + kcol];
            pa0[1] = PwU[(g +  8) * PSS + kcol];
            pa0[2] = PwU[ g       * PSS + kcol + 4];
            pa0[3] = PwU[(g +  8) * PSS + kcol + 4];
            pa1[0] = PwU[(g + 16) * PSS + kcol];
            pa1[1] = PwU[(g + 24) * PSS + kcol];
            pa1[2] = PwU[(g + 16) * PSS + kcol + 4];
            pa1[3] = PwU[(g + 24) * PSS + kcol + 4];
            #pragma unroll
            for (int j = 0; j < 8; j++) {
                const uint32_t v0 = VsU[(kc * 8 + b)     * VSS + j * 8 + g];
                const uint32_t v1 = VsU[(kc * 8 + b + 4) * VSS + j * 8 + g];
                mma_tf32(&o[j][0], pa0, v0, v1);
                mma_tf32(&o[j][4], pa1, v0, v1);
            }
        }
        __syncwarp();  // Pw reads done before next iter's overwrite

        __syncthreads();  // everyone done reading this stage before it is re-filled
    }

    // ---- epilogue: normalize + store ----
    {
        float inv[4];
        #pragma unroll
        for (int i = 0; i < 4; i++) inv[i] = (lrun[i] > 0.0f) ? (1.0f / lrun[i]) : 0.0f;
        float* orow = out + ((size_t)head * QLEN + q0 + r0) * DIM;
        #pragma unroll
        for (int j = 0; j < 8; j++) {
            const int col = j * 8 + 2 * b;
            *(float2*)&orow[ 0 * DIM + col] = make_float2(o[j][0] * inv[0], o[j][1] * inv[0]);
            *(float2*)&orow[ 8 * DIM + col] = make_float2(o[j][2] * inv[1], o[j][3] * inv[1]);
            *(float2*)&orow[16 * DIM + col] = make_float2(o[j][4] * inv[2], o[j][5] * inv[2]);
            *(float2*)&orow[24 * DIM + col] = make_float2(o[j][6] * inv[3], o[j][7] * inv[3]);
        }
    }
}

extern "C" void kernel_launch(void* const* d_in, const int* in_sizes, int n_in,
                              void* d_out, int out_size)
{
    const float* qs = (const float*)d_in[0];
    const float* ks = (const float*)d_in[1];
    const float* vs = (const float*)d_in[2];
    const unsigned int* maskw = (const unsigned int*)d_in[3];
    float* out = (float*)d_out;

    // prepass: round K,V to tf32 into static scratch
    const int total4 = NHEAD * KLEN * DIM / 4;           // 1,048,576 float4s
    kv_round<<<total4 / 256, 256>>>(ks, vs);

    cudaFuncSetAttribute(fa_hmma_cpa, cudaFuncAttributeMaxDynamicSharedMemorySize, SMEM_BYTES);
    dim3 grid(QLEN / BQ, NHEAD);
    fa_hmma_cpa<<<grid, NTHREADS, SMEM_BYTES>>>(qs, maskw, out);
}